// round 14
// baseline (speedup 1.0000x reference)
#include <cuda_runtime.h>
#include <cuda_bf16.h>
#include <cstdint>

// ---------------------------------------------------------------------------
// Problem constants
// ---------------------------------------------------------------------------
#define VOCAB 50257
#define DIM   768
#define VPAD  50304            // ceil(VOCAB/128)*128
#define NTILE 6                // 768 / 128
#define NPAIRS_T 21            // upper-triangle 128x128 tiles (mi<=ni)
#define KSPLIT 14              // split-K -> 21*14 = 294 CTAs (2 per SM)
#define EPS_F 1.1920929e-7f    // jnp.finfo(float32).eps

#define KC 64                  // K (vocab) elements per pipeline stage
#define KCHUNKS (VPAD / KC)    // 786
#define STAGE_BYTES 32768      // A tile 16KB + B tile 16KB (64 rows x 256B each)
#define SMEM_K3 (3 * STAGE_BYTES)   // 96KB -> 2 CTAs/SM

// ---------------------------------------------------------------------------
// Device scratch (allocation-free: __device__ globals)
// ---------------------------------------------------------------------------
__device__ __align__(16) __nv_bfloat16 g_Wn[(size_t)VPAD * DIM];  // Wn, bf16, v-major
__device__ float  g_Diag[VOCAB];
__device__ float  g_G[DIM * DIM];          // Gram accumulator (upper triangle)
__device__ double g_acc[2];                // [0]=total_sq, [1]=diag_sq
__device__ unsigned g_done;                // 21-way finisher counter
__device__ int    g_tilecnt[NPAIRS_T];     // split-K completion counters

// ---------------------------------------------------------------------------
// PTX helpers (family-portable: cp.async / ldmatrix / mma.sync only)
// ---------------------------------------------------------------------------
__device__ __forceinline__ uint32_t smem_to_u32(const void* p) {
    uint32_t a;
    asm("{ .reg .u64 t; cvta.to.shared.u64 t, %1; cvt.u32.u64 %0, t; }" : "=r"(a) : "l"(p));
    return a;
}

__device__ __forceinline__ void cp_async16(uint32_t dst, const void* src) {
    asm volatile("cp.async.cg.shared.global [%0], [%1], 16;" :: "r"(dst), "l"(src));
}

// transposed ldmatrix: smem tile is [k][m] / [k][n]; fragments come out as
// the mma.row.col A/B layouts.
#define LDSM_X4T(r, addr) \
    asm volatile("ldmatrix.sync.aligned.m8n8.x4.trans.shared.b16 {%0,%1,%2,%3}, [%4];" \
        : "=r"((r)[0]), "=r"((r)[1]), "=r"((r)[2]), "=r"((r)[3]) : "r"(addr))

__device__ __forceinline__ void mma16816(float* c, const uint32_t* a, uint32_t b0, uint32_t b1) {
    asm volatile(
        "mma.sync.aligned.m16n8k16.row.col.f32.bf16.bf16.f32 "
        "{%0,%1,%2,%3}, {%4,%5,%6,%7}, {%8,%9}, {%0,%1,%2,%3};"
        : "+f"(c[0]), "+f"(c[1]), "+f"(c[2]), "+f"(c[3])
        : "r"(a[0]), "r"(a[1]), "r"(a[2]), "r"(a[3]), "r"(b0), "r"(b1));
}

// ---------------------------------------------------------------------------
// Kernel 1 (streaming prep): row stats + scale + bf16 quantize, row-major out.
// One warp per vocab row; fully-coalesced fp32 reads and 8B bf16 stores.
// Also zeroes g_G / g_acc / g_done / g_tilecnt.
// ---------------------------------------------------------------------------
__global__ void __launch_bounds__(256) prep_kernel(const float* __restrict__ W) {
    int tid = threadIdx.x;
    int wid = tid >> 5;
    int lane = tid & 31;

    // merged zero of scratch
    {
        int zi = blockIdx.x * 256 + tid;
        if (zi < DIM * DIM) g_G[zi] = 0.0f;
        if (blockIdx.x == 0) {
            if (tid < 2) g_acc[tid] = 0.0;
            if (tid == 2) g_done = 0u;
            if (tid >= 3 && tid < 3 + NPAIRS_T) g_tilecnt[tid - 3] = 0;
        }
    }

    int v = blockIdx.x * 8 + wid;          // grid = VPAD/8
    float4 x[6];
    if (v < VOCAB) {
        const float4* rp = (const float4*)(W + (size_t)v * DIM);
        #pragma unroll
        for (int j = 0; j < 6; j++) x[j] = rp[lane + j * 32];
    } else {
        #pragma unroll
        for (int j = 0; j < 6; j++) x[j] = make_float4(0.f, 0.f, 0.f, 0.f);
    }
    float ssum = 0.0f;
    #pragma unroll
    for (int j = 0; j < 6; j++)
        ssum += x[j].x * x[j].x + x[j].y * x[j].y + x[j].z * x[j].z + x[j].w * x[j].w;
    #pragma unroll
    for (int off = 16; off; off >>= 1) ssum += __shfl_xor_sync(0xffffffffu, ssum, off);

    float m = ssum * (1.0f / DIM) + EPS_F;
    float sc = rsqrtf(m);
    if (lane == 0 && v < VOCAB) g_Diag[v] = ssum / m;   // = ||wn_v||^2

    uint2* orow = (uint2*)(g_Wn + (size_t)v * DIM);
    #pragma unroll
    for (int j = 0; j < 6; j++) {
        __nv_bfloat162 lo = __float22bfloat162_rn(make_float2(x[j].x * sc, x[j].y * sc));
        __nv_bfloat162 hi = __float22bfloat162_rn(make_float2(x[j].z * sc, x[j].w * sc));
        uint2 pk;
        pk.x = *(const uint32_t*)&lo;
        pk.y = *(const uint32_t*)&hi;
        orow[lane + j * 32] = pk;
    }
}

// ---------------------------------------------------------------------------
// Kernel 2: bf16 Gram GEMM via mma.sync (m16n8k16) + ldmatrix.trans, with
// diagonal-warp skip and fused tail reduction.
// Smem tiles are k-major ([64 k][128 m] / [64 k][128 n], 256B rows, swizzled).
// 3-stage cp.async pipeline (prefetch distance 2), 96KB smem -> 2 CTAs/SM.
// CTA: one 128x128 tile (mi<=ni) x one of 14 K-splits. 8 warps, 64x32 each.
// The last split-CTA of each tile reduces that G tile (element-wise triangle
// weights); tile 0's finisher also reduces diag^2; the 21st finisher writes
// the final scalar.
// ---------------------------------------------------------------------------
__global__ void __launch_bounds__(256, 2) gram_kernel(float* __restrict__ out) {
    extern __shared__ char smem[];
    uint32_t sbase = smem_to_u32(smem);
    int tid = threadIdx.x;
    int wid = tid >> 5;
    int lane = tid & 31;

    // decode (mi, ni) with mi <= ni, and K split range
    int t_idx = blockIdx.x % NPAIRS_T;
    int split = blockIdx.x / NPAIRS_T;
    int t = t_idx;
    int mi = 0;
    while (t >= NTILE - mi) { t -= NTILE - mi; mi++; }
    int ni = mi + t;
    int c0 = (split * KCHUNKS) / KSPLIT;
    int c1 = ((split + 1) * KCHUNKS) / KSPLIT;
    int nk = c1 - c0;

    const int moff = mi * 128;
    const int noff = ni * 128;

    int ld_row = tid >> 4;          // 0..15
    int ld_ch  = tid & 15;          // 16B chunk within 256B row

    float acc[4][4][4];
    #pragma unroll
    for (int a = 0; a < 4; a++)
        #pragma unroll
        for (int b = 0; b < 4; b++)
            #pragma unroll
            for (int c = 0; c < 4; c++) acc[a][b][c] = 0.0f;

    int warp_m = wid >> 2;          // 0..1
    int warp_n = wid & 3;           // 0..3
    int mbase = warp_m * 64;
    int nbase = warp_n * 32;
    // diagonal tiles: warps covering m in [64,128) x n in [0,64) are strictly
    // below the diagonal; their output has weight 0 -> skip their MMA work.
    bool active = !(mi == ni && warp_m == 1 && warp_n < 2);
    int sub = lane >> 3;
    int r8  = lane & 7;

    // per-warp LDSM offsets within a stage tile (k-major, swizzled).
    uint32_t a_off[4];
    #pragma unroll
    for (int mt = 0; mt < 4; mt++) {
        int mcol = mbase + mt * 16 + (sub & 1) * 8;
        int ch = mcol >> 3;
        a_off[mt] = (uint32_t)(((sub >> 1) * 8 + r8) * 256) + (uint32_t)((ch ^ r8) * 16);
    }
    uint32_t b_off[2];
    #pragma unroll
    for (int np = 0; np < 2; np++) {
        int ncol = nbase + np * 16 + (sub >> 1) * 8;
        int ch = ncol >> 3;
        b_off[np] = (uint32_t)(((sub & 1) * 8 + r8) * 256) + (uint32_t)((ch ^ r8) * 16);
    }

    // prologue: fill 2 stages (prefetch distance 2)
    #pragma unroll 1
    for (int s = 0; s < 2; s++) {
        if (s < nk) {
            uint32_t stA = sbase + s * STAGE_BYTES;
            uint32_t stB = stA + 16384;
            size_t kbase = (size_t)(c0 + s) * KC;
            #pragma unroll
            for (int i = 0; i < 4; i++) {
                int row = ld_row + i * 16;
                uint32_t d = (uint32_t)row * 256 + (uint32_t)((ld_ch ^ (row & 7)) * 16);
                const __nv_bfloat16* src = g_Wn + (kbase + row) * DIM + ld_ch * 8;
                cp_async16(stA + d, src + moff);
                cp_async16(stB + d, src + noff);
            }
        }
        asm volatile("cp.async.commit_group;");
    }

    int buf = 0;
    #pragma unroll 1
    for (int it = 0; it < nk; it++) {
        asm volatile("cp.async.wait_group 1;");
        __syncthreads();

        uint32_t stA = sbase + buf * STAGE_BYTES;
        uint32_t stB = stA + 16384;

        if (active) {
            #pragma unroll
            for (int ks = 0; ks < 4; ks++) {
                uint32_t a[4][4], b[2][4];
                uint32_t kofs = (uint32_t)ks * 4096;    // 16 k-rows * 256B
                #pragma unroll
                for (int mt = 0; mt < 4; mt++) LDSM_X4T(a[mt], stA + a_off[mt] + kofs);
                #pragma unroll
                for (int np = 0; np < 2; np++) LDSM_X4T(b[np], stB + b_off[np] + kofs);
                #pragma unroll
                for (int mt = 0; mt < 4; mt++)
                    #pragma unroll
                    for (int nt = 0; nt < 4; nt++)
                        mma16816(acc[mt][nt], a[mt],
                                 b[nt >> 1][(nt & 1) * 2], b[nt >> 1][(nt & 1) * 2 + 1]);
            }
        }

        // prefetch stage it+2 into buffer (buf+2)%3 (freed last iter)
        if (it + 2 < nk) {
            int s = it + 2;
            int pb = buf + 2; if (pb >= 3) pb -= 3;
            uint32_t pA = sbase + pb * STAGE_BYTES;
            uint32_t pB = pA + 16384;
            size_t kbase = (size_t)(c0 + s) * KC;
            #pragma unroll
            for (int i = 0; i < 4; i++) {
                int row = ld_row + i * 16;
                uint32_t d = (uint32_t)row * 256 + (uint32_t)((ld_ch ^ (row & 7)) * 16);
                const __nv_bfloat16* src = g_Wn + (kbase + row) * DIM + ld_ch * 8;
                cp_async16(pA + d, src + moff);
                cp_async16(pB + d, src + noff);
            }
        }
        asm volatile("cp.async.commit_group;");
        if (++buf == 3) buf = 0;
    }

    // epilogue: merge split-K partials into g_G (skipped warps add nothing)
    if (active) {
        int g = lane >> 2;
        int tt = lane & 3;
        #pragma unroll
        for (int mt = 0; mt < 4; mt++) {
            int m = mi * 128 + mbase + mt * 16 + g;
            #pragma unroll
            for (int nt = 0; nt < 4; nt++) {
                int n = ni * 128 + nbase + nt * 8 + tt * 2;
                float* p0 = g_G + (size_t)m * DIM + n;
                float* p1 = g_G + (size_t)(m + 8) * DIM + n;
                atomicAdd(p0 + 0, acc[mt][nt][0]);
                atomicAdd(p0 + 1, acc[mt][nt][1]);
                atomicAdd(p1 + 0, acc[mt][nt][2]);
                atomicAdd(p1 + 1, acc[mt][nt][3]);
            }
        }
    }

    // ---- fused tail reduction: last split-CTA of each tile reduces it ----
    __shared__ int s_last;
    __threadfence();                       // release our partials
    __syncthreads();
    if (tid == 0) s_last = (atomicAdd(&g_tilecnt[t_idx], 1) == KSPLIT - 1);
    __syncthreads();
    if (!s_last) return;
    __threadfence();                       // acquire other CTAs' partials

    double accT = 0.0, accD = 0.0;
    const float* Gt = g_G + (size_t)(mi * 128) * DIM + ni * 128;
    if (mi < ni) {
        #pragma unroll 4
        for (int e = tid; e < 16384; e += 256) {
            int r = e >> 7, c = e & 127;
            double g = (double)__ldcg(Gt + (size_t)r * DIM + c);
            accT += 2.0 * g * g;
        }
    } else {
        #pragma unroll 4
        for (int e = tid; e < 16384; e += 256) {
            int r = e >> 7, c = e & 127;
            double g = (double)__ldcg(Gt + (size_t)r * DIM + c);
            double w = (r < c) ? 2.0 : (r == c ? 1.0 : 0.0);
            accT += w * g * g;
        }
    }
    if (t_idx == 0) {
        for (int v = tid; v < VOCAB; v += 256) {
            double d = (double)g_Diag[v];
            accD += d * d;
        }
    }
    #pragma unroll
    for (int off = 16; off; off >>= 1) {
        accT += __shfl_xor_sync(0xffffffffu, accT, off);
        accD += __shfl_xor_sync(0xffffffffu, accD, off);
    }
    __shared__ double sT[8], sD[8];
    __shared__ bool s_fin;
    if (lane == 0) { sT[wid] = accT; sD[wid] = accD; }
    __syncthreads();
    if (tid == 0) {
        double tT = 0.0, tD = 0.0;
        #pragma unroll
        for (int i = 0; i < 8; i++) { tT += sT[i]; tD += sD[i]; }
        atomicAdd(&g_acc[0], tT);
        if (t_idx == 0) atomicAdd(&g_acc[1], tD);
        __threadfence();
        unsigned prev = atomicAdd(&g_done, 1u);
        s_fin = (prev == NPAIRS_T - 1);
    }
    __syncthreads();
    if (s_fin && tid == 0) {
        __threadfence();
        double a0 = __ldcg(&g_acc[0]);
        double a1 = __ldcg(&g_acc[1]);
        double n_pairs = (double)VOCAB * (double)(VOCAB - 1) * 0.5;
        out[0] = (float)((a0 - a1) * 0.5 / n_pairs);
    }
}

// ---------------------------------------------------------------------------
// Launch
// ---------------------------------------------------------------------------
extern "C" void kernel_launch(void* const* d_in, const int* in_sizes, int n_in,
                              void* d_out, int out_size) {
    (void)in_sizes; (void)n_in; (void)out_size;
    const float* W = (const float*)d_in[0];
    float* out = (float*)d_out;

    cudaFuncSetAttribute(gram_kernel, cudaFuncAttributeMaxDynamicSharedMemorySize, SMEM_K3);

    prep_kernel<<<VPAD / 8, 256>>>(W);
    gram_kernel<<<NPAIRS_T * KSPLIT, 256, SMEM_K3>>>(out);
}

// round 15
// speedup vs baseline: 1.3428x; 1.3428x over previous
#include <cuda_runtime.h>
#include <cuda_bf16.h>
#include <cstdint>

// ---------------------------------------------------------------------------
// Problem constants
// ---------------------------------------------------------------------------
#define VOCAB 50257
#define DIM   768
#define VPAD  50304            // ceil(VOCAB/128)*128
#define NTILE 6                // 768 / 128
#define NPAIRS_T 21            // upper-triangle 128x128 tiles (mi<=ni)
#define KSPLIT 14              // split-K -> 21*14 = 294 CTAs (2 per SM)
#define EPS_F 1.1920929e-7f    // jnp.finfo(float32).eps

#define KC 64                  // K (vocab) elements per pipeline stage
#define KCHUNKS (VPAD / KC)    // 786
#define STAGE_BYTES 32768      // A tile 16KB + B tile 16KB (64 rows x 256B each)
#define SMEM_K3 (3 * STAGE_BYTES)   // 96KB -> 2 CTAs/SM

#define REDUCE_GRID 256

// ---------------------------------------------------------------------------
// Device scratch (allocation-free: __device__ globals)
// ---------------------------------------------------------------------------
__device__ __align__(16) __nv_bfloat16 g_Wn[(size_t)VPAD * DIM];  // Wn, bf16, v-major
__device__ float  g_Diag[VOCAB];
__device__ float  g_G[DIM * DIM];          // Gram accumulator (upper triangle)
__device__ double g_acc[2];                // [0]=total_sq, [1]=diag_sq
__device__ unsigned g_done;                // last-block flag for fused finalize

// ---------------------------------------------------------------------------
// PTX helpers (family-portable: cp.async / ldmatrix / mma.sync only)
// ---------------------------------------------------------------------------
__device__ __forceinline__ uint32_t smem_to_u32(const void* p) {
    uint32_t a;
    asm("{ .reg .u64 t; cvta.to.shared.u64 t, %1; cvt.u32.u64 %0, t; }" : "=r"(a) : "l"(p));
    return a;
}

__device__ __forceinline__ void cp_async16(uint32_t dst, const void* src) {
    asm volatile("cp.async.cg.shared.global [%0], [%1], 16;" :: "r"(dst), "l"(src));
}

// transposed ldmatrix: smem tile is [k][m] / [k][n]; fragments come out as
// the mma.row.col A/B layouts.
#define LDSM_X4T(r, addr) \
    asm volatile("ldmatrix.sync.aligned.m8n8.x4.trans.shared.b16 {%0,%1,%2,%3}, [%4];" \
        : "=r"((r)[0]), "=r"((r)[1]), "=r"((r)[2]), "=r"((r)[3]) : "r"(addr))

__device__ __forceinline__ void mma16816(float* c, const uint32_t* a, uint32_t b0, uint32_t b1) {
    asm volatile(
        "mma.sync.aligned.m16n8k16.row.col.f32.bf16.bf16.f32 "
        "{%0,%1,%2,%3}, {%4,%5,%6,%7}, {%8,%9}, {%0,%1,%2,%3};"
        : "+f"(c[0]), "+f"(c[1]), "+f"(c[2]), "+f"(c[3])
        : "r"(a[0]), "r"(a[1]), "r"(a[2]), "r"(a[3]), "r"(b0), "r"(b1));
}

// ---------------------------------------------------------------------------
// Kernel 1 (streaming prep): row stats + scale + bf16 quantize, row-major out.
// One warp per vocab row; fully-coalesced fp32 reads and 8B bf16 stores.
// Also zeroes g_G / g_acc / g_done.
// ---------------------------------------------------------------------------
__global__ void __launch_bounds__(256) prep_kernel(const float* __restrict__ W) {
    int tid = threadIdx.x;
    int wid = tid >> 5;
    int lane = tid & 31;

    // merged zero of scratch
    {
        int zi = blockIdx.x * 256 + tid;
        if (zi < DIM * DIM) g_G[zi] = 0.0f;
        if (blockIdx.x == 0 && tid < 2) g_acc[tid] = 0.0;
        if (blockIdx.x == 0 && tid == 2) g_done = 0u;
    }

    int v = blockIdx.x * 8 + wid;          // grid = VPAD/8
    float4 x[6];
    if (v < VOCAB) {
        const float4* rp = (const float4*)(W + (size_t)v * DIM);
        #pragma unroll
        for (int j = 0; j < 6; j++) x[j] = rp[lane + j * 32];
    } else {
        #pragma unroll
        for (int j = 0; j < 6; j++) x[j] = make_float4(0.f, 0.f, 0.f, 0.f);
    }
    float ssum = 0.0f;
    #pragma unroll
    for (int j = 0; j < 6; j++)
        ssum += x[j].x * x[j].x + x[j].y * x[j].y + x[j].z * x[j].z + x[j].w * x[j].w;
    #pragma unroll
    for (int off = 16; off; off >>= 1) ssum += __shfl_xor_sync(0xffffffffu, ssum, off);

    float m = ssum * (1.0f / DIM) + EPS_F;
    float sc = rsqrtf(m);
    if (lane == 0 && v < VOCAB) g_Diag[v] = ssum / m;   // = ||wn_v||^2

    uint2* orow = (uint2*)(g_Wn + (size_t)v * DIM);
    #pragma unroll
    for (int j = 0; j < 6; j++) {
        __nv_bfloat162 lo = __float22bfloat162_rn(make_float2(x[j].x * sc, x[j].y * sc));
        __nv_bfloat162 hi = __float22bfloat162_rn(make_float2(x[j].z * sc, x[j].w * sc));
        uint2 pk;
        pk.x = *(const uint32_t*)&lo;
        pk.y = *(const uint32_t*)&hi;
        orow[lane + j * 32] = pk;
    }
}

// ---------------------------------------------------------------------------
// Kernel 2: bf16 Gram GEMM via mma.sync (m16n8k16) + ldmatrix.trans.
// Exact R11 structure (129.5us baseline) + diagonal-warp skip only.
// Smem tiles are k-major ([64 k][128 m] / [64 k][128 n], 256B rows, swizzled).
// 3-stage cp.async pipeline (prefetch distance 2), 96KB smem -> 2 CTAs/SM.
// CTA: one 128x128 tile (mi<=ni) x one of 14 K-splits. 8 warps, 64x32 each.
// ---------------------------------------------------------------------------
__global__ void __launch_bounds__(256, 2) gram_kernel() {
    extern __shared__ char smem[];
    uint32_t sbase = smem_to_u32(smem);
    int tid = threadIdx.x;
    int wid = tid >> 5;
    int lane = tid & 31;

    // decode (mi, ni) with mi <= ni, and K split range
    int t = blockIdx.x % NPAIRS_T;
    int split = blockIdx.x / NPAIRS_T;
    int mi = 0;
    while (t >= NTILE - mi) { t -= NTILE - mi; mi++; }
    int ni = mi + t;
    int c0 = (split * KCHUNKS) / KSPLIT;
    int c1 = ((split + 1) * KCHUNKS) / KSPLIT;
    int nk = c1 - c0;

    const int moff = mi * 128;
    const int noff = ni * 128;

    int ld_row = tid >> 4;          // 0..15
    int ld_ch  = tid & 15;          // 16B chunk within 256B row

    float acc[4][4][4];
    #pragma unroll
    for (int a = 0; a < 4; a++)
        #pragma unroll
        for (int b = 0; b < 4; b++)
            #pragma unroll
            for (int c = 0; c < 4; c++) acc[a][b][c] = 0.0f;

    int warp_m = wid >> 2;          // 0..1
    int warp_n = wid & 3;           // 0..3
    int mbase = warp_m * 64;
    int nbase = warp_n * 32;
    // diagonal tiles: warps covering m in [64,128) x n in [0,64) are strictly
    // below the diagonal; those outputs carry weight 0 in the reduce -> skip.
    bool active = !(mi == ni && warp_m == 1 && warp_n < 2);
    int sub = lane >> 3;
    int r8  = lane & 7;

    // per-warp LDSM offsets within a stage tile (k-major, swizzled).
    uint32_t a_off[4];
    #pragma unroll
    for (int mt = 0; mt < 4; mt++) {
        int mcol = mbase + mt * 16 + (sub & 1) * 8;
        int ch = mcol >> 3;
        a_off[mt] = (uint32_t)(((sub >> 1) * 8 + r8) * 256) + (uint32_t)((ch ^ r8) * 16);
    }
    uint32_t b_off[2];
    #pragma unroll
    for (int np = 0; np < 2; np++) {
        int ncol = nbase + np * 16 + (sub >> 1) * 8;
        int ch = ncol >> 3;
        b_off[np] = (uint32_t)(((sub & 1) * 8 + r8) * 256) + (uint32_t)((ch ^ r8) * 16);
    }

    // prologue: fill 2 stages (prefetch distance 2)
    #pragma unroll 1
    for (int s = 0; s < 2; s++) {
        if (s < nk) {
            uint32_t stA = sbase + s * STAGE_BYTES;
            uint32_t stB = stA + 16384;
            size_t kbase = (size_t)(c0 + s) * KC;
            #pragma unroll
            for (int i = 0; i < 4; i++) {
                int row = ld_row + i * 16;
                uint32_t d = (uint32_t)row * 256 + (uint32_t)((ld_ch ^ (row & 7)) * 16);
                const __nv_bfloat16* src = g_Wn + (kbase + row) * DIM + ld_ch * 8;
                cp_async16(stA + d, src + moff);
                cp_async16(stB + d, src + noff);
            }
        }
        asm volatile("cp.async.commit_group;");
    }

    int buf = 0;
    #pragma unroll 1
    for (int it = 0; it < nk; it++) {
        asm volatile("cp.async.wait_group 1;");
        __syncthreads();

        uint32_t stA = sbase + buf * STAGE_BYTES;
        uint32_t stB = stA + 16384;

        if (active) {
            #pragma unroll
            for (int ks = 0; ks < 4; ks++) {
                uint32_t a[4][4], b[2][4];
                uint32_t kofs = (uint32_t)ks * 4096;    // 16 k-rows * 256B
                #pragma unroll
                for (int mt = 0; mt < 4; mt++) LDSM_X4T(a[mt], stA + a_off[mt] + kofs);
                #pragma unroll
                for (int np = 0; np < 2; np++) LDSM_X4T(b[np], stB + b_off[np] + kofs);
                #pragma unroll
                for (int mt = 0; mt < 4; mt++)
                    #pragma unroll
                    for (int nt = 0; nt < 4; nt++)
                        mma16816(acc[mt][nt], a[mt],
                                 b[nt >> 1][(nt & 1) * 2], b[nt >> 1][(nt & 1) * 2 + 1]);
            }
        }

        // prefetch stage it+2 into buffer (buf+2)%3 (freed last iter)
        if (it + 2 < nk) {
            int s = it + 2;
            int pb = buf + 2; if (pb >= 3) pb -= 3;
            uint32_t pA = sbase + pb * STAGE_BYTES;
            uint32_t pB = pA + 16384;
            size_t kbase = (size_t)(c0 + s) * KC;
            #pragma unroll
            for (int i = 0; i < 4; i++) {
                int row = ld_row + i * 16;
                uint32_t d = (uint32_t)row * 256 + (uint32_t)((ld_ch ^ (row & 7)) * 16);
                const __nv_bfloat16* src = g_Wn + (kbase + row) * DIM + ld_ch * 8;
                cp_async16(pA + d, src + moff);
                cp_async16(pB + d, src + noff);
            }
        }
        asm volatile("cp.async.commit_group;");
        if (++buf == 3) buf = 0;
    }

    // epilogue: merge split-K partials into g_G (skipped warps add nothing)
    if (active) {
        int g = lane >> 2;
        int tt = lane & 3;
        #pragma unroll
        for (int mt = 0; mt < 4; mt++) {
            int m = mi * 128 + mbase + mt * 16 + g;
            #pragma unroll
            for (int nt = 0; nt < 4; nt++) {
                int n = ni * 128 + nbase + nt * 8 + tt * 2;
                float* p0 = g_G + (size_t)m * DIM + n;
                float* p1 = g_G + (size_t)(m + 8) * DIM + n;
                atomicAdd(p0 + 0, acc[mt][nt][0]);
                atomicAdd(p0 + 1, acc[mt][nt][1]);
                atomicAdd(p1 + 0, acc[mt][nt][2]);
                atomicAdd(p1 + 1, acc[mt][nt][3]);
            }
        }
    }
}

// ---------------------------------------------------------------------------
// Kernel 3 (fused reduce+finalize): element-wise triangle weights —
// total_sq = 2*sum_{i<j} G_ij^2 + sum_i G_ii^2 (lower entries never read),
// diag_sq = sum over vocab of ||wn_v||^4. Last block finalizes the scalar.
// ---------------------------------------------------------------------------
__global__ void reduce_kernel(float* __restrict__ out) {
    const int n1 = DIM * DIM;
    const int tot = n1 + VOCAB;
    double accT = 0.0, accD = 0.0;
    for (int idx = blockIdx.x * 256 + threadIdx.x; idx < tot; idx += REDUCE_GRID * 256) {
        if (idx < n1) {
            int i = idx / DIM;
            int j = idx - i * DIM;
            double g = (double)g_G[idx];
            double w = (i < j) ? 2.0 : (i == j ? 1.0 : 0.0);
            accT += w * g * g;
        } else {
            double d = (double)g_Diag[idx - n1];
            accD += d * d;
        }
    }
    #pragma unroll
    for (int off = 16; off; off >>= 1) {
        accT += __shfl_xor_sync(0xffffffffu, accT, off);
        accD += __shfl_xor_sync(0xffffffffu, accD, off);
    }
    __shared__ double sT[8], sD[8];
    __shared__ bool is_last;
    if ((threadIdx.x & 31) == 0) { sT[threadIdx.x >> 5] = accT; sD[threadIdx.x >> 5] = accD; }
    __syncthreads();
    if (threadIdx.x == 0) {
        double tT = 0.0, tD = 0.0;
        #pragma unroll
        for (int i = 0; i < 8; i++) { tT += sT[i]; tD += sD[i]; }
        atomicAdd(&g_acc[0], tT);
        atomicAdd(&g_acc[1], tD);
        __threadfence();
        unsigned prev = atomicAdd(&g_done, 1u);
        is_last = (prev == REDUCE_GRID - 1);
    }
    __syncthreads();
    if (is_last && threadIdx.x == 0) {
        double n_pairs = (double)VOCAB * (double)(VOCAB - 1) * 0.5;
        out[0] = (float)((g_acc[0] - g_acc[1]) * 0.5 / n_pairs);
    }
}

// ---------------------------------------------------------------------------
// Launch
// ---------------------------------------------------------------------------
extern "C" void kernel_launch(void* const* d_in, const int* in_sizes, int n_in,
                              void* d_out, int out_size) {
    (void)in_sizes; (void)n_in; (void)out_size;
    const float* W = (const float*)d_in[0];
    float* out = (float*)d_out;

    cudaFuncSetAttribute(gram_kernel, cudaFuncAttributeMaxDynamicSharedMemorySize, SMEM_K3);

    prep_kernel<<<VPAD / 8, 256>>>(W);
    gram_kernel<<<NPAIRS_T * KSPLIT, 256, SMEM_K3>>>();
    reduce_kernel<<<REDUCE_GRID, 256>>>(out);
}